// round 12
// baseline (speedup 1.0000x reference)
#include <cuda_runtime.h>
#include <cstdint>

// Fixed problem shapes: E<=4096, IN=OUT=256, N_NODES=1024
#define MAX_E 4096
#define NN    1024
#define FC    256
#define FC4   64
#define NT    256
#define SLABS 32           // channel slabs (blocks in k_t)
#define CPS   8            // channels per slab (SLABS*CPS == FC)

// ---------------- global scratch ----------------
// g_hist/g_sl: zeroed by loader for run 1, reset at tail of k_y for replays.
// g_flags: sticky OR of a deterministic input property -> no reset needed.
__device__ int   g_hist[NN];    // src count low 16 bits, dst count high 16 bits
__device__ int   g_sl[NN];      // self-loop count
__device__ int   g_flags;       // bit0: any nonzero byte, bit1: misaligned nonzero
__device__ float g_w[MAX_E];
__device__ float g_t[NN * FC];
__device__ float g_T[NN * FC];

// ============ K0: global histogram + layout flags ==========================
__global__ __launch_bounds__(NT)
void k_hist(const int* __restrict__ ei, const unsigned char* __restrict__ bb,
            int E) {
    int e = blockIdx.x * NT + threadIdx.x;
    if (e >= E) return;
    int s = ei[e], d = ei[E + e];
    atomicAdd(&g_hist[s], 1);
    atomicAdd(&g_hist[d], 0x10000);
    if (s == d) atomicAdd(&g_sl[s], 1);
    unsigned char v = bb[e];
    if (v) atomicOr(&g_flags, (e & 3) ? 3 : 1);
}

// ============ K1: t = B(w .* x) via channel-slab smem scatter ==============
// 32 blocks; block b owns channels [b*8, b*8+8). No global float atomics.
__global__ __launch_bounds__(NT)
void k_t(const float* __restrict__ x, const int* __restrict__ ei,
         const unsigned char* __restrict__ bb, int E) {
    __shared__ float ts[NN * CPS];          // 32 KB
    const int tid = threadIdx.x;
    const int b   = blockIdx.x;
    const int c0  = b * CPS;

    for (int i = tid; i < NN * CPS; i += NT) ts[i] = 0.0f;
    __syncthreads();

    const int flags = g_flags;
    for (int e = tid; e < E; e += NT) {
        int s = ei[e], d = ei[E + e];
        float w = 0.0f;
        if (s != d) {
            int hs = g_hist[s], hd = g_hist[d];
            int deg = (hs & 0xffff) + (hs >> 16)
                    + (hd & 0xffff) + (hd >> 16)
                    - 2 * (g_sl[s] + g_sl[d]);
            int dir;
            if (flags & 2)      dir = bb[e] != 0;               // byte layout
            else if (flags & 1) dir = ((const int*)bb)[e] != 0; // int layout
            else                dir = 0;
            w = (dir ? -1.0f : 1.0f) * rsqrtf((float)deg);
        }
        if (b == (e & (SLABS - 1))) g_w[e] = w;   // unique writer per edge
        if (w != 0.0f) {
            const float4* xp = (const float4*)&x[(size_t)e * FC + c0];
            float4 v0 = xp[0], v1 = xp[1];
            float* ps = &ts[s * CPS];
            float* pd = &ts[d * CPS];
            atomicAdd(&ps[0], -w * v0.x); atomicAdd(&ps[1], -w * v0.y);
            atomicAdd(&ps[2], -w * v0.z); atomicAdd(&ps[3], -w * v0.w);
            atomicAdd(&ps[4], -w * v1.x); atomicAdd(&ps[5], -w * v1.y);
            atomicAdd(&ps[6], -w * v1.z); atomicAdd(&ps[7], -w * v1.w);
            atomicAdd(&pd[0],  w * v0.x); atomicAdd(&pd[1],  w * v0.y);
            atomicAdd(&pd[2],  w * v0.z); atomicAdd(&pd[3],  w * v0.w);
            atomicAdd(&pd[4],  w * v1.x); atomicAdd(&pd[5],  w * v1.y);
            atomicAdd(&pd[6],  w * v1.z); atomicAdd(&pd[7],  w * v1.w);
        }
    }
    __syncthreads();

    for (int n = tid; n < NN; n += NT) {
        float4 a = *(float4*)&ts[n * CPS];
        float4 c = *(float4*)&ts[n * CPS + 4];
        *(float4*)&g_t[(size_t)n * FC + c0]     = a;
        *(float4*)&g_t[(size_t)n * FC + c0 + 4] = c;
    }
}

// ============ K2: GEMM  T = t @ W^T  (M=1024, N=256, K=256) ================
__global__ __launch_bounds__(NT)
void k_gemm(const float* __restrict__ W) {
    __shared__ float As[16][33];
    __shared__ float Bs[16][65];
    const int tid = threadIdx.x;
    const int b   = blockIdx.x;
    int gx = b & 3, gy = b >> 2;
    int m0 = gy * 32, n0 = gx * 64;
    int tx = tid & 15, ty = tid >> 4;

    float acc[2][4];
    #pragma unroll
    for (int i = 0; i < 2; i++)
        #pragma unroll
        for (int j = 0; j < 4; j++) acc[i][j] = 0.0f;

    for (int k0 = 0; k0 < FC; k0 += 16) {
        if (tid < 128) {                   // A tile 32x16
            int row = tid >> 2, kq = (tid & 3) << 2;
            float4 v = *(const float4*)&g_t[(m0 + row) * FC + k0 + kq];
            As[kq + 0][row] = v.x; As[kq + 1][row] = v.y;
            As[kq + 2][row] = v.z; As[kq + 3][row] = v.w;
        }
        {                                  // B tile 64x16
            int n = tid >> 2, kq = (tid & 3) << 2;
            float4 v = *(const float4*)&W[(n0 + n) * FC + k0 + kq];
            Bs[kq + 0][n] = v.x; Bs[kq + 1][n] = v.y;
            Bs[kq + 2][n] = v.z; Bs[kq + 3][n] = v.w;
        }
        __syncthreads();
        #pragma unroll
        for (int k = 0; k < 16; k++) {
            float a0 = As[k][ty * 2 + 0];
            float a1 = As[k][ty * 2 + 1];
            float w4[4];
            #pragma unroll
            for (int j = 0; j < 4; j++) w4[j] = Bs[k][tx * 4 + j];
            #pragma unroll
            for (int j = 0; j < 4; j++) {
                acc[0][j] = fmaf(a0, w4[j], acc[0][j]);
                acc[1][j] = fmaf(a1, w4[j], acc[1][j]);
            }
        }
        __syncthreads();
    }
    #pragma unroll
    for (int i = 0; i < 2; i++) {
        float4 v = make_float4(acc[i][0], acc[i][1], acc[i][2], acc[i][3]);
        *(float4*)&g_T[(m0 + ty * 2 + i) * FC + n0 + tx * 4] = v;
    }
}

// ============ K3: y_e = w_e * (T[dst_e] - T[src_e])  + scratch reset =======
__global__ __launch_bounds__(NT)
void k_y(const int* __restrict__ ei, float* __restrict__ y, int E) {
    int i = blockIdx.x * NT + threadIdx.x;
    if (i < E * FC4) {
        int e = i >> 6, c4 = i & 63;
        float w = g_w[e];
        int s = ei[e], d = ei[E + e];
        float4 vd = ((const float4*)g_T)[d * FC4 + c4];
        float4 vs = ((const float4*)g_T)[s * FC4 + c4];
        float4 o;
        o.x = w * (vd.x - vs.x); o.y = w * (vd.y - vs.y);
        o.z = w * (vd.z - vs.z); o.w = w * (vd.w - vs.w);
        ((float4*)y)[i] = o;
    }
    // reset histogram scratch for the next graph replay
    if (blockIdx.x == 0) {
        for (int k = threadIdx.x; k < NN; k += NT) { g_hist[k] = 0; g_sl[k] = 0; }
    }
}

// ---------------- launch ---------------------------------------------------
extern "C" void kernel_launch(void* const* d_in, const int* in_sizes, int n_in,
                              void* d_out, int out_size) {
    const float* x     = (const float*)d_in[0];   // [E, 256]
    const float* W     = (const float*)d_in[1];   // [256, 256]
    const int*   ei    = (const int*)d_in[2];     // [2, E]
    const void*  isdir = d_in[3];                 // [E] bool or int32

    int E = in_sizes[2] / 2;
    float* y = (float*)d_out;

    k_hist<<<(E + NT - 1) / NT, NT>>>(ei, (const unsigned char*)isdir, E);
    k_t<<<SLABS, NT>>>(x, ei, (const unsigned char*)isdir, E);
    k_gemm<<<128, NT>>>(W);
    k_y<<<(E * FC4 + NT - 1) / NT, NT>>>(ei, y, E);
}

// round 13
// speedup vs baseline: 2.5895x; 2.5895x over previous
#include <cuda_runtime.h>
#include <cstdint>

// Fixed problem shapes: E<=4096, IN=OUT=256, N_NODES=1024
#define MAX_E 4096
#define NN    1024
#define FC    256
#define FC4   64
#define NT    256

// ---------------- global scratch ----------------
__device__ int   g_hist[NN];    // src count low 16 bits, dst count high 16 bits
__device__ int   g_sl[NN];      // self-loop count
__device__ int   g_flags;       // bit0: any nonzero byte, bit1: misaligned nonzero (sticky)
__device__ float g_w[MAX_E];
__device__ float g_t[NN * FC];
__device__ float g_T[NN * FC];

__device__ __forceinline__ void red_add_v4(float* p, float a, float b,
                                           float c, float d) {
    asm volatile("red.global.add.v4.f32 [%0], {%1, %2, %3, %4};"
                 :: "l"(p), "f"(a), "f"(b), "f"(c), "f"(d)
                 : "memory");
}

// ============ K0: zero accumulators + hist scratch (replay-safe) ===========
__global__ __launch_bounds__(NT)
void k_zero() {
    int i = blockIdx.x * NT + threadIdx.x;          // 256 blocks -> 65536
    ((float4*)g_t)[i] = make_float4(0.f, 0.f, 0.f, 0.f);
    if (i < NN) { g_hist[i] = 0; g_sl[i] = 0; }
}

// ============ K1: global histogram + layout flags ==========================
__global__ __launch_bounds__(NT)
void k_hist(const int* __restrict__ ei, const unsigned char* __restrict__ bb,
            int E) {
    int e = blockIdx.x * NT + threadIdx.x;
    if (e >= E) return;
    int s = ei[e], d = ei[E + e];
    atomicAdd(&g_hist[s], 1);
    atomicAdd(&g_hist[d], 0x10000);
    if (s == d) atomicAdd(&g_sl[s], 1);
    unsigned char v = bb[e];
    if (v) atomicOr(&g_flags, (e & 3) ? 3 : 1);
}

// ============ K2: scatter  t[src] -= w*x, t[dst] += w*x  (v4 REDs) =========
// 64 threads per edge (one float4 chunk each); weight computed warp-uniform.
__global__ __launch_bounds__(NT)
void k_scatter(const float* __restrict__ x, const int* __restrict__ ei,
               const unsigned char* __restrict__ bb, int E) {
    int i = blockIdx.x * NT + threadIdx.x;
    if (i >= E * FC4) return;
    int e  = i >> 6;
    int c4 = i & 63;

    int s = ei[e], d = ei[E + e];           // warp-uniform loads (broadcast)
    float w = 0.0f;
    if (s != d) {
        int hs = g_hist[s], hd = g_hist[d];
        int deg = (hs & 0xffff) + (hs >> 16)
                + (hd & 0xffff) + (hd >> 16)
                - 2 * (g_sl[s] + g_sl[d]);
        int flags = g_flags;
        int dir;
        if (flags & 2)      dir = bb[e] != 0;               // byte layout
        else if (flags & 1) dir = ((const int*)bb)[e] != 0; // int layout
        else                dir = 0;
        w = (dir ? -1.0f : 1.0f) * rsqrtf((float)deg);
    }
    if (c4 == 0) g_w[e] = w;
    if (w == 0.0f) return;

    float4 v = ((const float4*)x)[e * FC4 + c4];
    float* ps = &g_t[(size_t)s * FC + c4 * 4];
    float* pd = &g_t[(size_t)d * FC + c4 * 4];
    red_add_v4(ps, -w * v.x, -w * v.y, -w * v.z, -w * v.w);
    red_add_v4(pd,  w * v.x,  w * v.y,  w * v.z,  w * v.w);
}

// ============ K3: GEMM  T = t @ W^T  (M=1024, N=256, K=256) ================
__global__ __launch_bounds__(NT)
void k_gemm(const float* __restrict__ W) {
    __shared__ float As[16][33];
    __shared__ float Bs[16][65];
    const int tid = threadIdx.x;
    const int b   = blockIdx.x;
    int gx = b & 3, gy = b >> 2;
    int m0 = gy * 32, n0 = gx * 64;
    int tx = tid & 15, ty = tid >> 4;

    float acc[2][4];
    #pragma unroll
    for (int i = 0; i < 2; i++)
        #pragma unroll
        for (int j = 0; j < 4; j++) acc[i][j] = 0.0f;

    for (int k0 = 0; k0 < FC; k0 += 16) {
        if (tid < 128) {                   // A tile 32x16
            int row = tid >> 2, kq = (tid & 3) << 2;
            float4 v = *(const float4*)&g_t[(m0 + row) * FC + k0 + kq];
            As[kq + 0][row] = v.x; As[kq + 1][row] = v.y;
            As[kq + 2][row] = v.z; As[kq + 3][row] = v.w;
        }
        {                                  // B tile 64x16
            int n = tid >> 2, kq = (tid & 3) << 2;
            float4 v = *(const float4*)&W[(n0 + n) * FC + k0 + kq];
            Bs[kq + 0][n] = v.x; Bs[kq + 1][n] = v.y;
            Bs[kq + 2][n] = v.z; Bs[kq + 3][n] = v.w;
        }
        __syncthreads();
        #pragma unroll
        for (int k = 0; k < 16; k++) {
            float a0 = As[k][ty * 2 + 0];
            float a1 = As[k][ty * 2 + 1];
            float w4[4];
            #pragma unroll
            for (int j = 0; j < 4; j++) w4[j] = Bs[k][tx * 4 + j];
            #pragma unroll
            for (int j = 0; j < 4; j++) {
                acc[0][j] = fmaf(a0, w4[j], acc[0][j]);
                acc[1][j] = fmaf(a1, w4[j], acc[1][j]);
            }
        }
        __syncthreads();
    }
    #pragma unroll
    for (int i = 0; i < 2; i++) {
        float4 v = make_float4(acc[i][0], acc[i][1], acc[i][2], acc[i][3]);
        *(float4*)&g_T[(m0 + ty * 2 + i) * FC + n0 + tx * 4] = v;
    }
}

// ============ K4: y_e = w_e * (T[dst_e] - T[src_e]) ========================
__global__ __launch_bounds__(NT)
void k_y(const int* __restrict__ ei, float* __restrict__ y, int E) {
    int i = blockIdx.x * NT + threadIdx.x;
    if (i >= E * FC4) return;
    int e = i >> 6, c4 = i & 63;
    float w = g_w[e];
    int s = ei[e], d = ei[E + e];
    float4 vd = ((const float4*)g_T)[d * FC4 + c4];
    float4 vs = ((const float4*)g_T)[s * FC4 + c4];
    float4 o;
    o.x = w * (vd.x - vs.x); o.y = w * (vd.y - vs.y);
    o.z = w * (vd.z - vs.z); o.w = w * (vd.w - vs.w);
    ((float4*)y)[i] = o;
}

// ---------------- launch ---------------------------------------------------
extern "C" void kernel_launch(void* const* d_in, const int* in_sizes, int n_in,
                              void* d_out, int out_size) {
    const float* x     = (const float*)d_in[0];   // [E, 256]
    const float* W     = (const float*)d_in[1];   // [256, 256]
    const int*   ei    = (const int*)d_in[2];     // [2, E]
    const void*  isdir = d_in[3];                 // [E] bool or int32

    int E = in_sizes[2] / 2;
    float* y = (float*)d_out;

    k_zero<<<256, NT>>>();
    k_hist<<<(E + NT - 1) / NT, NT>>>(ei, (const unsigned char*)isdir, E);
    k_scatter<<<(E * FC4 + NT - 1) / NT, NT>>>(x, ei, (const unsigned char*)isdir, E);
    k_gemm<<<128, NT>>>(W);
    k_y<<<(E * FC4 + NT - 1) / NT, NT>>>(ei, y, E);
}

// round 14
// speedup vs baseline: 3.1459x; 1.2149x over previous
#include <cuda_runtime.h>
#include <cstdint>

// Fixed problem shapes: E<=4096, IN=OUT=256, N_NODES=1024
#define MAX_E 4096
#define NN    1024
#define FC    256
#define FC4   64
#define NT    256

// ---------------- global scratch ----------------
__device__ int   g_hist[NN];    // src count low 16 bits, dst count high 16 bits
__device__ int   g_sl[NN];      // self-loop count
__device__ int   g_flags;       // bit0: any nonzero byte, bit1: misaligned nonzero (sticky)
__device__ float g_w[MAX_E];
__device__ float g_t[NN * FC];
__device__ float g_T[NN * FC];

__device__ __forceinline__ void red_add_v4(float* p, float a, float b,
                                           float c, float d) {
    asm volatile("red.global.add.v4.f32 [%0], {%1, %2, %3, %4};"
                 :: "l"(p), "f"(a), "f"(b), "f"(c), "f"(d)
                 : "memory");
}

// ============ K0: zero accumulators + hist scratch (replay-safe) ===========
__global__ __launch_bounds__(NT)
void k_zero() {
    int i = blockIdx.x * NT + threadIdx.x;          // 256 blocks -> 65536
    ((float4*)g_t)[i] = make_float4(0.f, 0.f, 0.f, 0.f);
    if (i < NN) { g_hist[i] = 0; g_sl[i] = 0; }
}

// ============ K1: global histogram + layout flags ==========================
__global__ __launch_bounds__(NT)
void k_hist(const int* __restrict__ ei, const unsigned char* __restrict__ bb,
            int E) {
    int e = blockIdx.x * NT + threadIdx.x;
    if (e >= E) return;
    int s = ei[e], d = ei[E + e];
    atomicAdd(&g_hist[s], 1);
    atomicAdd(&g_hist[d], 0x10000);
    if (s == d) atomicAdd(&g_sl[s], 1);
    unsigned char v = bb[e];
    if (v) atomicOr(&g_flags, (e & 3) ? 3 : 1);
}

// ============ K2: scatter  t[src] -= w*x, t[dst] += w*x  (v4 REDs) =========
__global__ __launch_bounds__(NT)
void k_scatter(const float* __restrict__ x, const int* __restrict__ ei,
               const unsigned char* __restrict__ bb, int E) {
    int i = blockIdx.x * NT + threadIdx.x;
    if (i >= E * FC4) return;
    int e  = i >> 6;
    int c4 = i & 63;

    int s = ei[e], d = ei[E + e];           // warp-uniform loads (broadcast)
    float w = 0.0f;
    if (s != d) {
        int hs = g_hist[s], hd = g_hist[d];
        int deg = (hs & 0xffff) + (hs >> 16)
                + (hd & 0xffff) + (hd >> 16)
                - 2 * (g_sl[s] + g_sl[d]);
        int flags = g_flags;
        int dir;
        if (flags & 2)      dir = bb[e] != 0;               // byte layout
        else if (flags & 1) dir = ((const int*)bb)[e] != 0; // int layout
        else                dir = 0;
        w = (dir ? -1.0f : 1.0f) * rsqrtf((float)deg);
    }
    if (c4 == 0) g_w[e] = w;
    if (w == 0.0f) return;

    float4 v = ((const float4*)x)[e * FC4 + c4];
    float* ps = &g_t[(size_t)s * FC + c4 * 4];
    float* pd = &g_t[(size_t)d * FC + c4 * 4];
    red_add_v4(ps, -w * v.x, -w * v.y, -w * v.z, -w * v.w);
    red_add_v4(pd,  w * v.x,  w * v.y,  w * v.z,  w * v.w);
}

// ============ K3: GEMM  T = t @ W^T  (M=1024, N=256, K=256) ================
// 128 blocks x 128 threads; 32x64 tile; 4x4 register tile per thread; BK=32.
#define GBK 32
__global__ __launch_bounds__(128)
void k_gemm(const float* __restrict__ W) {
    __shared__ float As[GBK][33];     // [k][m]
    __shared__ float Bs[GBK][65];     // [k][n]
    const int tid = threadIdx.x;
    const int b   = blockIdx.x;
    int gx = b & 3, gy = b >> 2;
    int m0 = gy * 32, n0 = gx * 64;
    int tx = tid & 15;                // 16 col groups (x4 = 64)
    int ty = tid >> 4;                // 8 row groups (x4 = 32)

    float acc[4][4];
    #pragma unroll
    for (int i = 0; i < 4; i++)
        #pragma unroll
        for (int j = 0; j < 4; j++) acc[i][j] = 0.0f;

    for (int k0 = 0; k0 < FC; k0 += GBK) {
        // A tile: 32 rows x 32 k = 256 float4, 2 per thread
        #pragma unroll
        for (int r = 0; r < 2; r++) {
            int idx = tid + 128 * r;
            int row = idx >> 3;
            int kq  = (idx & 7) << 2;
            float4 v = *(const float4*)&g_t[(m0 + row) * FC + k0 + kq];
            As[kq + 0][row] = v.x; As[kq + 1][row] = v.y;
            As[kq + 2][row] = v.z; As[kq + 3][row] = v.w;
        }
        // B tile: 64 n x 32 k = 512 float4, 4 per thread
        #pragma unroll
        for (int r = 0; r < 4; r++) {
            int idx = tid + 128 * r;
            int n   = idx >> 3;
            int kq  = (idx & 7) << 2;
            float4 v = *(const float4*)&W[(n0 + n) * FC + k0 + kq];
            Bs[kq + 0][n] = v.x; Bs[kq + 1][n] = v.y;
            Bs[kq + 2][n] = v.z; Bs[kq + 3][n] = v.w;
        }
        __syncthreads();

        #pragma unroll
        for (int k = 0; k < GBK; k++) {
            float a[4], bb4[4];
            #pragma unroll
            for (int i = 0; i < 4; i++) a[i]   = As[k][ty * 4 + i];
            #pragma unroll
            for (int j = 0; j < 4; j++) bb4[j] = Bs[k][tx * 4 + j];
            #pragma unroll
            for (int i = 0; i < 4; i++)
                #pragma unroll
                for (int j = 0; j < 4; j++)
                    acc[i][j] = fmaf(a[i], bb4[j], acc[i][j]);
        }
        __syncthreads();
    }

    #pragma unroll
    for (int i = 0; i < 4; i++) {
        float4 v = make_float4(acc[i][0], acc[i][1], acc[i][2], acc[i][3]);
        *(float4*)&g_T[(m0 + ty * 4 + i) * FC + n0 + tx * 4] = v;
    }
}

// ============ K4: y_e = w_e * (T[dst_e] - T[src_e]) ========================
__global__ __launch_bounds__(NT)
void k_y(const int* __restrict__ ei, float* __restrict__ y, int E) {
    int i = blockIdx.x * NT + threadIdx.x;
    if (i >= E * FC4) return;
    int e = i >> 6, c4 = i & 63;
    float w = g_w[e];
    int s = ei[e], d = ei[E + e];
    float4 vd = ((const float4*)g_T)[d * FC4 + c4];
    float4 vs = ((const float4*)g_T)[s * FC4 + c4];
    float4 o;
    o.x = w * (vd.x - vs.x); o.y = w * (vd.y - vs.y);
    o.z = w * (vd.z - vs.z); o.w = w * (vd.w - vs.w);
    ((float4*)y)[i] = o;
}

// ---------------- launch ---------------------------------------------------
extern "C" void kernel_launch(void* const* d_in, const int* in_sizes, int n_in,
                              void* d_out, int out_size) {
    const float* x     = (const float*)d_in[0];   // [E, 256]
    const float* W     = (const float*)d_in[1];   // [256, 256]
    const int*   ei    = (const int*)d_in[2];     // [2, E]
    const void*  isdir = d_in[3];                 // [E] bool or int32

    int E = in_sizes[2] / 2;
    float* y = (float*)d_out;

    k_zero<<<256, NT>>>();
    k_hist<<<(E + NT - 1) / NT, NT>>>(ei, (const unsigned char*)isdir, E);
    k_scatter<<<(E * FC4 + NT - 1) / NT, NT>>>(x, ei, (const unsigned char*)isdir, E);
    k_gemm<<<128, 128>>>(W);
    k_y<<<(E * FC4 + NT - 1) / NT, NT>>>(ei, y, E);
}

// round 15
// speedup vs baseline: 3.6375x; 1.1563x over previous
#include <cuda_runtime.h>
#include <cstdint>

// Fixed problem shapes: E<=4096, IN=OUT=256, N_NODES=1024
#define MAX_E 4096
#define NN    1024
#define FC    256
#define FC4   64
#define NT    256

// ---------------- global scratch ----------------
__device__ int   g_hist[NN];    // src count low 16 bits, dst count high 16 bits
__device__ int   g_sl[NN];      // self-loop count
__device__ int   g_flags;       // bit0: any nonzero byte, bit1: misaligned nonzero (sticky)
__device__ float g_w[MAX_E];
__device__ float g_t[NN * FC];
__device__ float g_T[NN * FC];

__device__ __forceinline__ void red_add_v4(float* p, float a, float b,
                                           float c, float d) {
    asm volatile("red.global.add.v4.f32 [%0], {%1, %2, %3, %4};"
                 :: "l"(p), "f"(a), "f"(b), "f"(c), "f"(d)
                 : "memory");
}

// ============ K0: zero accumulators + hist scratch (replay-safe) ===========
__global__ __launch_bounds__(NT)
void k_zero() {
    int i = blockIdx.x * NT + threadIdx.x;          // 256 blocks -> 65536
    ((float4*)g_t)[i] = make_float4(0.f, 0.f, 0.f, 0.f);
    if (i < NN) { g_hist[i] = 0; g_sl[i] = 0; }
}

// ============ K1: global histogram + layout flags ==========================
__global__ __launch_bounds__(NT)
void k_hist(const int* __restrict__ ei, const unsigned char* __restrict__ bb,
            int E) {
    int e = blockIdx.x * NT + threadIdx.x;
    if (e >= E) return;
    int s = ei[e], d = ei[E + e];
    atomicAdd(&g_hist[s], 1);
    atomicAdd(&g_hist[d], 0x10000);
    if (s == d) atomicAdd(&g_sl[s], 1);
    unsigned char v = bb[e];
    if (v) atomicOr(&g_flags, (e & 3) ? 3 : 1);
}

// ============ K2: scatter  t[src] -= w*x, t[dst] += w*x  (v4 REDs) =========
__global__ __launch_bounds__(NT)
void k_scatter(const float* __restrict__ x, const int* __restrict__ ei,
               const unsigned char* __restrict__ bb, int E) {
    int i = blockIdx.x * NT + threadIdx.x;
    if (i >= E * FC4) return;
    int e  = i >> 6;
    int c4 = i & 63;

    int s = ei[e], d = ei[E + e];           // warp-uniform loads (broadcast)
    float w = 0.0f;
    if (s != d) {
        int hs = g_hist[s], hd = g_hist[d];
        int deg = (hs & 0xffff) + (hs >> 16)
                + (hd & 0xffff) + (hd >> 16)
                - 2 * (g_sl[s] + g_sl[d]);
        int flags = g_flags;
        int dir;
        if (flags & 2)      dir = bb[e] != 0;               // byte layout
        else if (flags & 1) dir = ((const int*)bb)[e] != 0; // int layout
        else                dir = 0;
        w = (dir ? -1.0f : 1.0f) * rsqrtf((float)deg);
    }
    if (c4 == 0) g_w[e] = w;
    if (w == 0.0f) return;

    float4 v = ((const float4*)x)[e * FC4 + c4];
    float* ps = &g_t[(size_t)s * FC + c4 * 4];
    float* pd = &g_t[(size_t)d * FC + c4 * 4];
    red_add_v4(ps, -w * v.x, -w * v.y, -w * v.z, -w * v.w);
    red_add_v4(pd,  w * v.x,  w * v.y,  w * v.z,  w * v.w);
}

// ============ K3: GEMM  T = t @ W^T  (M=1024, N=256, K=256) ================
// 128 blocks x 256 threads. Tile 32x64, 4x4/thread. In-block split-K:
// warps 0-3 do k in [0,128), warps 4-7 do [128,256); smem reduce at end.
#define GP_A 36     // A row pad (floats, multiple of 4 -> 16B-aligned rows)
#define GP_B 33     // B row pad (floats, odd -> conflict-free scalar reads)
__global__ __launch_bounds__(256)
void k_gemm(const float* __restrict__ W) {
    __shared__ float As[2][32][GP_A];
    __shared__ float Bs[2][64][GP_B];
    __shared__ float Red[32 * 64];
    const int tid  = threadIdx.x;
    const int b    = blockIdx.x;
    const int gx   = b & 3, gy = b >> 2;
    const int m0   = gy * 32, n0 = gx * 64;
    const int half = tid >> 7;          // 0 or 1 (k-half owner)
    const int hid  = tid & 127;
    const int tx   = hid & 15;          // 16 col groups x4 = 64
    const int ty   = hid >> 4;          // 8 row groups x4 = 32

    float acc[4][4];
    #pragma unroll
    for (int i = 0; i < 4; i++)
        #pragma unroll
        for (int j = 0; j < 4; j++) acc[i][j] = 0.0f;

    for (int it = 0; it < 4; it++) {
        const int k0 = it * 32;
        // A: 2 halves x 32 rows x 32 k = 512 float4; 2 per thread
        #pragma unroll
        for (int r = 0; r < 2; r++) {
            int idx = tid + 256 * r;         // 0..511
            int h   = idx >> 8;
            int rem = idx & 255;
            int row = rem >> 3;
            int kq  = (rem & 7) << 2;
            float4 v = *(const float4*)&g_t[(m0 + row) * FC + h * 128 + k0 + kq];
            *(float4*)&As[h][row][kq] = v;
        }
        // B: 2 halves x 64 n x 32 k = 1024 float4; 4 per thread (scalar STS)
        #pragma unroll
        for (int r = 0; r < 4; r++) {
            int idx = tid + 256 * r;         // 0..1023
            int h   = idx >> 9;
            int rem = idx & 511;
            int n   = rem >> 3;
            int kq  = (rem & 7) << 2;
            float4 v = *(const float4*)&W[(n0 + n) * FC + h * 128 + k0 + kq];
            Bs[h][n][kq + 0] = v.x; Bs[h][n][kq + 1] = v.y;
            Bs[h][n][kq + 2] = v.z; Bs[h][n][kq + 3] = v.w;
        }
        __syncthreads();

        #pragma unroll
        for (int kk = 0; kk < 32; kk += 4) {
            float4 a4[4];
            #pragma unroll
            for (int i = 0; i < 4; i++)
                a4[i] = *(const float4*)&As[half][ty * 4 + i][kk];
            float bv[4];
            // dk = 0
            #pragma unroll
            for (int j = 0; j < 4; j++) bv[j] = Bs[half][tx * 4 + j][kk + 0];
            #pragma unroll
            for (int i = 0; i < 4; i++) {
                acc[i][0] = fmaf(a4[i].x, bv[0], acc[i][0]);
                acc[i][1] = fmaf(a4[i].x, bv[1], acc[i][1]);
                acc[i][2] = fmaf(a4[i].x, bv[2], acc[i][2]);
                acc[i][3] = fmaf(a4[i].x, bv[3], acc[i][3]);
            }
            // dk = 1
            #pragma unroll
            for (int j = 0; j < 4; j++) bv[j] = Bs[half][tx * 4 + j][kk + 1];
            #pragma unroll
            for (int i = 0; i < 4; i++) {
                acc[i][0] = fmaf(a4[i].y, bv[0], acc[i][0]);
                acc[i][1] = fmaf(a4[i].y, bv[1], acc[i][1]);
                acc[i][2] = fmaf(a4[i].y, bv[2], acc[i][2]);
                acc[i][3] = fmaf(a4[i].y, bv[3], acc[i][3]);
            }
            // dk = 2
            #pragma unroll
            for (int j = 0; j < 4; j++) bv[j] = Bs[half][tx * 4 + j][kk + 2];
            #pragma unroll
            for (int i = 0; i < 4; i++) {
                acc[i][0] = fmaf(a4[i].z, bv[0], acc[i][0]);
                acc[i][1] = fmaf(a4[i].z, bv[1], acc[i][1]);
                acc[i][2] = fmaf(a4[i].z, bv[2], acc[i][2]);
                acc[i][3] = fmaf(a4[i].z, bv[3], acc[i][3]);
            }
            // dk = 3
            #pragma unroll
            for (int j = 0; j < 4; j++) bv[j] = Bs[half][tx * 4 + j][kk + 3];
            #pragma unroll
            for (int i = 0; i < 4; i++) {
                acc[i][0] = fmaf(a4[i].w, bv[0], acc[i][0]);
                acc[i][1] = fmaf(a4[i].w, bv[1], acc[i][1]);
                acc[i][2] = fmaf(a4[i].w, bv[2], acc[i][2]);
                acc[i][3] = fmaf(a4[i].w, bv[3], acc[i][3]);
            }
        }
        __syncthreads();
    }

    // merge the two k-halves
    if (half == 1) {
        #pragma unroll
        for (int i = 0; i < 4; i++)
            *(float4*)&Red[(ty * 4 + i) * 64 + tx * 4] =
                make_float4(acc[i][0], acc[i][1], acc[i][2], acc[i][3]);
    }
    __syncthreads();
    if (half == 0) {
        #pragma unroll
        for (int i = 0; i < 4; i++) {
            float4 r = *(const float4*)&Red[(ty * 4 + i) * 64 + tx * 4];
            float4 v = make_float4(acc[i][0] + r.x, acc[i][1] + r.y,
                                   acc[i][2] + r.z, acc[i][3] + r.w);
            *(float4*)&g_T[(m0 + ty * 4 + i) * FC + n0 + tx * 4] = v;
        }
    }
}

// ============ K4: y_e = w_e * (T[dst_e] - T[src_e])  (2 elems/thread) ======
__global__ __launch_bounds__(NT)
void k_y(const int* __restrict__ ei, float* __restrict__ y, int E) {
    const int Nel   = E * FC4;
    const int halfN = Nel >> 1;
    int i0 = blockIdx.x * NT + threadIdx.x;
    if (i0 >= halfN) return;
    int i1 = i0 + halfN;

    int e0 = i0 >> 6, c0 = i0 & 63;
    int e1 = i1 >> 6, c1 = i1 & 63;
    int s0 = ei[e0], d0 = ei[E + e0];
    int s1 = ei[e1], d1 = ei[E + e1];
    float w0 = g_w[e0], w1 = g_w[e1];

    float4 vd0 = ((const float4*)g_T)[d0 * FC4 + c0];
    float4 vs0 = ((const float4*)g_T)[s0 * FC4 + c0];
    float4 vd1 = ((const float4*)g_T)[d1 * FC4 + c1];
    float4 vs1 = ((const float4*)g_T)[s1 * FC4 + c1];

    float4 o0, o1;
    o0.x = w0 * (vd0.x - vs0.x); o0.y = w0 * (vd0.y - vs0.y);
    o0.z = w0 * (vd0.z - vs0.z); o0.w = w0 * (vd0.w - vs0.w);
    o1.x = w1 * (vd1.x - vs1.x); o1.y = w1 * (vd1.y - vs1.y);
    o1.z = w1 * (vd1.z - vs1.z); o1.w = w1 * (vd1.w - vs1.w);
    ((float4*)y)[i0] = o0;
    ((float4*)y)[i1] = o1;
}

// ---------------- launch ---------------------------------------------------
extern "C" void kernel_launch(void* const* d_in, const int* in_sizes, int n_in,
                              void* d_out, int out_size) {
    const float* x     = (const float*)d_in[0];   // [E, 256]
    const float* W     = (const float*)d_in[1];   // [256, 256]
    const int*   ei    = (const int*)d_in[2];     // [2, E]
    const void*  isdir = d_in[3];                 // [E] bool or int32

    int E = in_sizes[2] / 2;
    float* y = (float*)d_out;

    k_zero<<<256, NT>>>();
    k_hist<<<(E + NT - 1) / NT, NT>>>(ei, (const unsigned char*)isdir, E);
    k_scatter<<<(E * FC4 + NT - 1) / NT, NT>>>(x, ei, (const unsigned char*)isdir, E);
    k_gemm<<<128, 256>>>(W);
    k_y<<<((E * FC4 / 2) + NT - 1) / NT, NT>>>(ei, y, E);
}